// round 11
// baseline (speedup 1.0000x reference)
#include <cuda_runtime.h>
#include <cuda_bf16.h>
#include <cooperative_groups.h>
#include <cstdint>

namespace cg = cooperative_groups;

#define T_SEQ 16384
#define D_IN  300
#define U_H   300
#define G4    1200
#define ADIM  350
#define R_ROWS 30
#define NCTA  15     // CTAs per direction (cluster size)

// ---------------- device scratch ----------------
__device__ float g_xp[2][(size_t)T_SEQ * G4];   // per-direction x@Wk+b
__device__ float g_H[(size_t)T_SEQ * 600];      // [hf | hb] per t
__device__ float g_L[(size_t)R_ROWS * T_SEQ];   // attention logits
__device__ float g_p[T_SEQ];                    // H[t] . dense_w
__device__ float g_acc;                         // sum over rows of (A_r . p)
__device__ int   g_flag[2][16];                 // per-(dir,rank) step flags (fallback path)

// ---------------- helpers ----------------
__device__ __forceinline__ float2 ffma2(float2 a, float2 b, float2 c) {
    union Cv { float2 f; unsigned long long u; };
    Cv ua, ub, uc, ud;
    ua.f = a; ub.f = b; uc.f = c;
    asm("fma.rn.f32x2 %0, %1, %2, %3;" : "=l"(ud.u) : "l"(ua.u), "l"(ub.u), "l"(uc.u));
    return ud.f;
}
__device__ __forceinline__ float sigm(float x) { return 1.0f / (1.0f + __expf(-x)); }

// ==================================================================
// Kernel 1: xp = x @ Wk + b for both directions (blockIdx.z selects).
// ==================================================================
__global__ void __launch_bounds__(256) k_gemm_xp(
    const float* __restrict__ X,
    const float* __restrict__ Wf, const float* __restrict__ bf,
    const float* __restrict__ Wb, const float* __restrict__ bb)
{
    if (blockIdx.x == 0 && blockIdx.y == 0 && blockIdx.z == 0 && threadIdx.x < 32) {
        g_flag[0][threadIdx.x % 16] = 0;
        g_flag[1][threadIdx.x % 16] = 0;
    }
    const int nt = blockIdx.x, mt = blockIdx.y, wsel = blockIdx.z;
    const float* B    = wsel ? Wb : Wf;
    const float* bias = wsel ? bb : bf;
    float* C = g_xp[wsel];

    __shared__ float As[16][64];
    __shared__ float Bs[16][64];

    const int tid = threadIdx.x;
    const int ty = tid / 16, tx = tid % 16;
    const int a_m  = tid >> 2, a_k4 = (tid & 3) * 4;
    const int b_k  = tid >> 4, b_n4 = (tid & 15) * 4;
    const int m0 = mt * 64, n0 = nt * 64;

    float2 acc[4][2];
#pragma unroll
    for (int i = 0; i < 4; i++) { acc[i][0] = make_float2(0.f,0.f); acc[i][1] = make_float2(0.f,0.f); }

    for (int k0 = 0; k0 < D_IN; k0 += 16) {
        float4 av = make_float4(0.f,0.f,0.f,0.f);
        if (k0 + a_k4 < D_IN)
            av = *(const float4*)&X[(size_t)(m0 + a_m) * D_IN + k0 + a_k4];
        float4 bv = make_float4(0.f,0.f,0.f,0.f);
        if ((k0 + b_k < D_IN) && (n0 + b_n4 < G4))
            bv = *(const float4*)&B[(size_t)(k0 + b_k) * G4 + n0 + b_n4];

        __syncthreads();
        As[a_k4 + 0][a_m] = av.x;
        As[a_k4 + 1][a_m] = av.y;
        As[a_k4 + 2][a_m] = av.z;
        As[a_k4 + 3][a_m] = av.w;
        *(float4*)&Bs[b_k][b_n4] = bv;
        __syncthreads();

#pragma unroll
        for (int kk = 0; kk < 16; kk++) {
            float4 a4 = *(const float4*)&As[kk][ty * 4];
            float4 b4 = *(const float4*)&Bs[kk][tx * 4];
            float2 b01 = make_float2(b4.x, b4.y);
            float2 b23 = make_float2(b4.z, b4.w);
            float2 aa;
            aa = make_float2(a4.x, a4.x); acc[0][0]=ffma2(aa,b01,acc[0][0]); acc[0][1]=ffma2(aa,b23,acc[0][1]);
            aa = make_float2(a4.y, a4.y); acc[1][0]=ffma2(aa,b01,acc[1][0]); acc[1][1]=ffma2(aa,b23,acc[1][1]);
            aa = make_float2(a4.z, a4.z); acc[2][0]=ffma2(aa,b01,acc[2][0]); acc[2][1]=ffma2(aa,b23,acc[2][1]);
            aa = make_float2(a4.w, a4.w); acc[3][0]=ffma2(aa,b01,acc[3][0]); acc[3][1]=ffma2(aa,b23,acc[3][1]);
        }
    }

#pragma unroll
    for (int i = 0; i < 4; i++) {
        const int m = m0 + ty * 4 + i;
#pragma unroll
        for (int j = 0; j < 2; j++) {
            const int n = n0 + tx * 4 + j * 2;
            if (n < G4) {
                float2 v = acc[i][j];
                v.x += bias[n];
                v.y += bias[n + 1];
                *(float2*)&C[(size_t)m * G4 + n] = v;
            }
        }
    }
}

// ==================================================================
// Kernel 2 (primary): cluster LSTM, 15 CTAs x 320 threads per dir.
// NO mbarrier: self-validating tagged slots. Slot u = {h[u], tag},
// tag = s+1 written by step s. Consumers spin per-lane on volatile
// LDS until tag == s. Double-buffered by step parity; WAR safe via
// tag transitivity. Producer pushes 16B v4 {h0,tag,h1,tag} per peer.
// ==================================================================
__global__ void __launch_bounds__(320, 1) k_lstm_cl(
    const float* __restrict__ Wr_f, const float* __restrict__ Wr_b)
{
    __shared__ __align__(16) float hbuf[2][640];   // [buf][u*2 + {h,tag}]

    cg::cluster_group cl = cg::this_cluster();
    const int tid  = threadIdx.x;
    const int warp = tid >> 5, lane = tid & 31;
    const int dir  = blockIdx.x / NCTA;
    const int rank = blockIdx.x % NCTA;
    const float* __restrict__ Wr = dir ? Wr_b : Wr_f;
    const float* __restrict__ xp = g_xp[dir];
    const int u0 = rank * 20 + 2 * warp;

    // register-resident weights: w[k][g] = Wr[k*32+lane][g*300 + u0 .. +1]
    float2 w[10][4];
#pragma unroll
    for (int k = 0; k < 10; k++) {
        const int uin = k * 32 + lane;
#pragma unroll
        for (int g = 0; g < 4; g++)
            w[k][g] = (uin < U_H) ? *(const float2*)&Wr[(size_t)uin * G4 + g * 300 + u0]
                                  : make_float2(0.f, 0.f);
    }

    // zero both buffers (tags become 0; valid tags start at 1)
    for (int i = tid; i < 1280; i += 320) ((float*)hbuf)[i] = 0.f;
    __syncthreads();
    cl.sync();   // all CTAs zeroed before any remote store

    const uint32_t lbase = (uint32_t)__cvta_generic_to_shared(&hbuf[0][0]);

    // remote slot base for this warp's pair (u0,u0+1) in peer rank = lane
    uint32_t rh0 = 0, rh1 = 0;
    if (lane < NCTA) {
        const uint32_t l0 = lbase + (uint32_t)(2 * u0) * 4u;          // buf0
        const uint32_t l1 = lbase + (uint32_t)(640 + 2 * u0) * 4u;    // buf1
        asm("mapa.shared::cluster.u32 %0, %1, %2;" : "=r"(rh0) : "r"(l0), "r"(lane));
        asm("mapa.shared::cluster.u32 %0, %1, %2;" : "=r"(rh1) : "r"(l1), "r"(lane));
    }

    float c = 0.f;            // cell state (lanes 0,1)
    const int lb0 = lane & 1;

    for (int s = 0; s < T_SEQ; s++) {
        const int t  = dir ? (T_SEQ - 1 - s) : s;
        const int wb = s & 1;            // buffer written by this step
        const int rb = wb ^ 1;           // buffer read (holds h(s-1), tag s)

        // xp loads — depend only on s; issue before the spin
        float x0 = 0.f, x1 = 0.f, x2 = 0.f, x3 = 0.f;
        if (lane < 2) {
            const float* p = &xp[(size_t)t * G4 + u0 + lane];
            x0 = __ldg(p); x1 = __ldg(p + 300); x2 = __ldg(p + 600); x3 = __ldg(p + 900);
        }

        float gv0 = 0.f, gv1 = 0.f, gv2 = 0.f, gv3 = 0.f;
        if (s > 0) {
            const uint32_t rbase = lbase + (uint32_t)(rb * 640) * 4u;
            float hv[10];
#pragma unroll
            for (int k = 0; k < 10; k++) {
                const int uin = k * 32 + lane;
                if (uin < U_H) {
                    const uint32_t addr = rbase + (uint32_t)(2 * uin) * 4u;
                    float vh, vt;
                    do {
                        asm volatile("ld.volatile.shared.v2.f32 {%0,%1}, [%2];"
                                     : "=f"(vh), "=f"(vt) : "r"(addr));
                    } while (__float_as_int(vt) != s);
                    hv[k] = vh;
                } else {
                    hv[k] = 0.f;
                }
            }

            float2 a0 = make_float2(0.f,0.f), a1 = a0, a2 = a0, a3 = a0;
#pragma unroll
            for (int k = 0; k < 10; k++) {
                const float2 hh = make_float2(hv[k], hv[k]);
                a0 = ffma2(hh, w[k][0], a0);
                a1 = ffma2(hh, w[k][1], a1);
                a2 = ffma2(hh, w[k][2], a2);
                a3 = ffma2(hh, w[k][3], a3);
            }

            // value-splitting reduction: column j total lands in lanes with
            // (lane&7)==j; 4 idx-shuffles gather the per-u gate totals.
            const bool b0 = lb0;
            float k0 = b0 ? a0.y : a0.x, d0 = b0 ? a0.x : a0.y;
            float k1 = b0 ? a1.y : a1.x, d1 = b0 ? a1.x : a1.y;
            float k2 = b0 ? a2.y : a2.x, d2 = b0 ? a2.x : a2.y;
            float k3 = b0 ? a3.y : a3.x, d3 = b0 ? a3.x : a3.y;
            k0 += __shfl_xor_sync(~0u, d0, 1);
            k1 += __shfl_xor_sync(~0u, d1, 1);
            k2 += __shfl_xor_sync(~0u, d2, 1);
            k3 += __shfl_xor_sync(~0u, d3, 1);

            const bool b1 = lane & 2;
            float m0 = b1 ? k1 : k0, e0 = b1 ? k0 : k1;
            float m1 = b1 ? k3 : k2, e1 = b1 ? k2 : k3;
            m0 += __shfl_xor_sync(~0u, e0, 2);
            m1 += __shfl_xor_sync(~0u, e1, 2);

            const bool b2 = lane & 4;
            float r = b2 ? m1 : m0, f = b2 ? m0 : m1;
            r += __shfl_xor_sync(~0u, f, 4);
            r += __shfl_xor_sync(~0u, r, 8);
            r += __shfl_xor_sync(~0u, r, 16);

            gv0 = __shfl_sync(~0u, r, lb0);
            gv1 = __shfl_sync(~0u, r, 2 + lb0);
            gv2 = __shfl_sync(~0u, r, 4 + lb0);
            gv3 = __shfl_sync(~0u, r, 6 + lb0);
        }

        float hval = 0.f;
        if (lane < 2) {
            const float zi = sigm(x0 + gv0);
            const float zf = sigm(x1 + gv1);
            const float zg = sigm(x2 + gv2);
            const float zo = sigm(x3 + gv3);
            c = zf * c + zi * zg;
            hval = zo * sigm(c);
        }
        const float h0 = __shfl_sync(~0u, hval, 0);
        const float h1 = __shfl_sync(~0u, hval, 1);

        // publish h(s) with tag s+1 into every CTA's write buffer
        if (s + 1 < T_SEQ && lane < NCTA) {
            const uint32_t rh = wb ? rh1 : rh0;
            const float ft = __int_as_float(s + 1);
            asm volatile("st.shared::cluster.v4.f32 [%0], {%1,%2,%3,%4};"
                         :: "r"(rh), "f"(h0), "f"(ft), "f"(h1), "f"(ft) : "memory");
        }

        if (lane == 0)
            *(float2*)&g_H[(size_t)t * 600 + dir * 300 + u0] = make_float2(h0, h1);
    }
}

// ==================================================================
// Kernel 2 (fallback): global-flag LSTM (no cluster), hot spin.
// ==================================================================
__global__ void __launch_bounds__(480, 1) k_lstm(
    const float* __restrict__ Wr_f, const float* __restrict__ Wr_b)
{
    const int tid  = threadIdx.x;
    const int warp = tid >> 5, lane = tid & 31;
    const int dir  = blockIdx.x / 10;
    const int rank = blockIdx.x % 10;
    const float* __restrict__ Wr = dir ? Wr_b : Wr_f;
    const float* __restrict__ xp = g_xp[dir];
    const int u0 = rank * 30 + 2 * warp;

    float2 w[10][4];
#pragma unroll
    for (int k = 0; k < 10; k++) {
        const int uin = k * 32 + lane;
#pragma unroll
        for (int g = 0; g < 4; g++)
            w[k][g] = (uin < U_H) ? *(const float2*)&Wr[(size_t)uin * G4 + g * 300 + u0]
                                  : make_float2(0.f, 0.f);
    }

    float c = 0.f;

    for (int s = 0; s < T_SEQ; s++) {
        const int t = dir ? (T_SEQ - 1 - s) : s;

        float x0 = 0.f, x1 = 0.f, x2 = 0.f, x3 = 0.f;
        if (lane < 2) {
            const float* p = &xp[(size_t)t * G4 + u0 + lane];
            x0 = __ldg(p); x1 = __ldg(p + 300); x2 = __ldg(p + 600); x3 = __ldg(p + 900);
        }

        float2 a0 = make_float2(0.f,0.f), a1 = a0, a2 = a0, a3 = a0;
        if (s > 0) {
            if (warp == 0 && lane < 10) {
                int v;
                const int* fp = &g_flag[dir][lane];
                do {
                    asm volatile("ld.acquire.gpu.s32 %0, [%1];" : "=r"(v) : "l"(fp));
                } while (v < s);
            }
            __syncthreads();

            const int tp = dir ? (t + 1) : (t - 1);
            const float* hrow = &g_H[(size_t)tp * 600 + dir * 300];
            float hv[10];
#pragma unroll
            for (int k = 0; k < 10; k++) {
                const int uin = k * 32 + lane;
                hv[k] = (uin < U_H) ? __ldcg(&hrow[uin]) : 0.f;
            }
#pragma unroll
            for (int k = 0; k < 10; k++) {
                const float2 hh = make_float2(hv[k], hv[k]);
                a0 = ffma2(hh, w[k][0], a0);
                a1 = ffma2(hh, w[k][1], a1);
                a2 = ffma2(hh, w[k][2], a2);
                a3 = ffma2(hh, w[k][3], a3);
            }
#pragma unroll
            for (int off = 16; off > 0; off >>= 1) {
                a0.x += __shfl_xor_sync(~0u, a0.x, off); a0.y += __shfl_xor_sync(~0u, a0.y, off);
                a1.x += __shfl_xor_sync(~0u, a1.x, off); a1.y += __shfl_xor_sync(~0u, a1.y, off);
                a2.x += __shfl_xor_sync(~0u, a2.x, off); a2.y += __shfl_xor_sync(~0u, a2.y, off);
                a3.x += __shfl_xor_sync(~0u, a3.x, off); a3.y += __shfl_xor_sync(~0u, a3.y, off);
            }
        }

        float hval = 0.f;
        if (lane < 2) {
            const float zi = sigm(x0 + (lane ? a0.y : a0.x));
            const float zf = sigm(x1 + (lane ? a1.y : a1.x));
            const float zg = sigm(x2 + (lane ? a2.y : a2.x));
            const float zo = sigm(x3 + (lane ? a3.y : a3.x));
            c = zf * c + zi * zg;
            hval = zo * sigm(c);
        }
        const float h0 = __shfl_sync(~0u, hval, 0);
        const float h1 = __shfl_sync(~0u, hval, 1);
        if (lane == 0)
            *(float2*)&g_H[(size_t)t * 600 + dir * 300 + u0] = make_float2(h0, h1);

        __syncthreads();
        if (tid == 0) {
            asm volatile("st.release.gpu.s32 [%0], %1;"
                         :: "l"(&g_flag[dir][rank]), "r"(s + 1) : "memory");
        }
    }
}

// ==================================================================
// Kernel 3: L = W2 @ tanh(W1 @ H^T)  (30 x T), fused.
// ==================================================================
#define TI 8
__global__ void __launch_bounds__(512) k_logits(
    const float* __restrict__ W1, const float* __restrict__ W2)
{
    __shared__ float Hs[600][TI];
    __shared__ float vs[ADIM][TI + 1];

    const int tid = threadIdx.x, lane = tid & 31, warp = tid >> 5;
    const int tchunk = blockIdx.x;

    for (int g = 0; g < 16; g++) {
        const int t0 = tchunk * 128 + g * TI;

        for (int i = tid; i < 600 * TI; i += 512) {
            const int tt = i / 600, k = i % 600;
            Hs[k][tt] = g_H[(size_t)(t0 + tt) * 600 + k];
        }
        __syncthreads();

        if (tid < ADIM) {
            float acc[TI];
#pragma unroll
            for (int q = 0; q < TI; q++) acc[q] = 0.f;
            const float* wrow = &W1[(size_t)tid * 600];
            for (int k = 0; k < 600; k++) {
                const float wv = __ldg(&wrow[k]);
                const float4 ha = *(const float4*)&Hs[k][0];
                const float4 hb = *(const float4*)&Hs[k][4];
                acc[0] += wv * ha.x; acc[1] += wv * ha.y;
                acc[2] += wv * ha.z; acc[3] += wv * ha.w;
                acc[4] += wv * hb.x; acc[5] += wv * hb.y;
                acc[6] += wv * hb.z; acc[7] += wv * hb.w;
            }
#pragma unroll
            for (int q = 0; q < TI; q++) vs[tid][q] = tanhf(acc[q]);
        }
        __syncthreads();

        for (int r = warp; r < R_ROWS; r += 16) {
            float acc[TI];
#pragma unroll
            for (int q = 0; q < TI; q++) acc[q] = 0.f;
            for (int a = lane; a < ADIM; a += 32) {
                const float wv = __ldg(&W2[(size_t)r * ADIM + a]);
#pragma unroll
                for (int q = 0; q < TI; q++) acc[q] += wv * vs[a][q];
            }
#pragma unroll
            for (int q = 0; q < TI; q++) {
#pragma unroll
                for (int off = 16; off > 0; off >>= 1)
                    acc[q] += __shfl_xor_sync(~0u, acc[q], off);
            }
            if (lane == 0) {
#pragma unroll
                for (int q = 0; q < TI; q++)
                    g_L[(size_t)r * T_SEQ + t0 + q] = acc[q];
            }
        }
        __syncthreads();
    }
}

// ==================================================================
// Kernel 4: p[t] = H[t,:] . dense_w ; also zero the scalar accumulator.
// ==================================================================
__global__ void __launch_bounds__(256) k_p(const float* __restrict__ dw)
{
    if (blockIdx.x == 0 && threadIdx.x == 0) g_acc = 0.f;
    const int warp = threadIdx.x >> 5, lane = threadIdx.x & 31;
    const int t = blockIdx.x * 8 + warp;
    float s = 0.f;
    const float* h = &g_H[(size_t)t * 600];
    for (int k = lane; k < 600; k += 32) s += h[k] * __ldg(&dw[k]);
#pragma unroll
    for (int o = 16; o > 0; o >>= 1) s += __shfl_xor_sync(~0u, s, o);
    if (lane == 0) g_p[t] = s;
}

// ==================================================================
// Kernel 5: per attention row r: softmax over T; accumulate A_r . p.
// ==================================================================
__global__ void __launch_bounds__(256) k_softmax_acc()
{
    const int r = blockIdx.x, tid = threadIdx.x;
    __shared__ float red[256];
    const float* L = &g_L[(size_t)r * T_SEQ];

    float m = -1e30f;
    for (int i = tid; i < T_SEQ; i += 256) m = fmaxf(m, L[i]);
    red[tid] = m; __syncthreads();
    for (int o = 128; o > 0; o >>= 1) {
        if (tid < o) red[tid] = fmaxf(red[tid], red[tid + o]);
        __syncthreads();
    }
    m = red[0]; __syncthreads();

    float se = 0.f, sp = 0.f;
    for (int i = tid; i < T_SEQ; i += 256) {
        const float e = __expf(L[i] - m);
        se += e;
        sp += e * g_p[i];
    }
    red[tid] = se; __syncthreads();
    for (int o = 128; o > 0; o >>= 1) {
        if (tid < o) red[tid] += red[tid + o];
        __syncthreads();
    }
    se = red[0]; __syncthreads();

    red[tid] = sp; __syncthreads();
    for (int o = 128; o > 0; o >>= 1) {
        if (tid < o) red[tid] += red[tid + o];
        __syncthreads();
    }
    if (tid == 0) atomicAdd(&g_acc, red[0] / se);
}

// ==================================================================
// Kernel 6: final scalar.
// ==================================================================
__global__ void k_final(const float* __restrict__ db, float* __restrict__ out)
{
    const float v = g_acc / 30.f + db[0];
    out[0] = 1.f / (1.f + expf(-v));
}

// ==================================================================
extern "C" void kernel_launch(void* const* d_in, const int* in_sizes, int n_in,
                              void* d_out, int out_size)
{
    const float* emb  = (const float*)d_in[0];
    const float* Wk_f = (const float*)d_in[1];
    const float* Wr_f = (const float*)d_in[2];
    const float* b_f  = (const float*)d_in[3];
    const float* Wk_b = (const float*)d_in[4];
    const float* Wr_b = (const float*)d_in[5];
    const float* b_b  = (const float*)d_in[6];
    const float* W1   = (const float*)d_in[7];
    const float* W2   = (const float*)d_in[8];
    const float* dw   = (const float*)d_in[9];
    const float* db   = (const float*)d_in[10];
    float* out = (float*)d_out;

    k_gemm_xp<<<dim3(19, 256, 2), 256>>>(emb, Wk_f, b_f, Wk_b, b_b);

    // Primary: cluster(NCTA) LSTM. Deterministic fallback if unsupported.
    cudaError_t e = cudaFuncSetAttribute(
        k_lstm_cl, cudaFuncAttributeNonPortableClusterSizeAllowed, 1);
    bool launched = false;
    if (e == cudaSuccess) {
        cudaLaunchConfig_t cfg = {};
        cfg.gridDim  = dim3(2 * NCTA, 1, 1);
        cfg.blockDim = dim3(320, 1, 1);
        cfg.dynamicSmemBytes = 0;
        cfg.stream = 0;
        cudaLaunchAttribute attrs[1];
        attrs[0].id = cudaLaunchAttributeClusterDimension;
        attrs[0].val.clusterDim.x = NCTA;
        attrs[0].val.clusterDim.y = 1;
        attrs[0].val.clusterDim.z = 1;
        cfg.attrs = attrs;
        cfg.numAttrs = 1;
        e = cudaLaunchKernelEx(&cfg, k_lstm_cl, Wr_f, Wr_b);
        launched = (e == cudaSuccess);
    }
    if (!launched) {
        cudaGetLastError();   // clear error state
        k_lstm<<<20, 480>>>(Wr_f, Wr_b);
    }

    k_logits<<<128, 512>>>(W1, W2);
    k_p<<<2048, 256>>>(dw);
    k_softmax_acc<<<30, 256>>>();
    k_final<<<1, 1>>>(db, out);
}

// round 12
// speedup vs baseline: 3.6646x; 3.6646x over previous
#include <cuda_runtime.h>
#include <cuda_bf16.h>
#include <cooperative_groups.h>
#include <cstdint>

namespace cg = cooperative_groups;

#define T_SEQ 16384
#define D_IN  300
#define U_H   300
#define G4    1200
#define ADIM  350
#define R_ROWS 30
#define NCTA  15     // CTAs per direction (cluster size)

// ---------------- device scratch ----------------
__device__ float g_xp[2][(size_t)T_SEQ * G4];   // per-direction x@Wk+b
__device__ float g_H[(size_t)T_SEQ * 600];      // [hf | hb] per t
__device__ float g_L[(size_t)R_ROWS * T_SEQ];   // attention logits
__device__ float g_p[T_SEQ];                    // H[t] . dense_w
__device__ float g_acc;                         // sum over rows of (A_r . p)
__device__ int   g_flag[2][16];                 // per-(dir,rank) step flags (fallback path)

// ---------------- helpers ----------------
__device__ __forceinline__ float2 ffma2(float2 a, float2 b, float2 c) {
    union Cv { float2 f; unsigned long long u; };
    Cv ua, ub, uc, ud;
    ua.f = a; ub.f = b; uc.f = c;
    asm("fma.rn.f32x2 %0, %1, %2, %3;" : "=l"(ud.u) : "l"(ua.u), "l"(ub.u), "l"(uc.u));
    return ud.f;
}
__device__ __forceinline__ float sigm(float x) { return 1.0f / (1.0f + __expf(-x)); }

// ==================================================================
// Kernel 1: xp = x @ Wk + b for both directions (blockIdx.z selects).
// ==================================================================
__global__ void __launch_bounds__(256) k_gemm_xp(
    const float* __restrict__ X,
    const float* __restrict__ Wf, const float* __restrict__ bf,
    const float* __restrict__ Wb, const float* __restrict__ bb)
{
    if (blockIdx.x == 0 && blockIdx.y == 0 && blockIdx.z == 0 && threadIdx.x < 32) {
        g_flag[0][threadIdx.x % 16] = 0;
        g_flag[1][threadIdx.x % 16] = 0;
    }
    const int nt = blockIdx.x, mt = blockIdx.y, wsel = blockIdx.z;
    const float* B    = wsel ? Wb : Wf;
    const float* bias = wsel ? bb : bf;
    float* C = g_xp[wsel];

    __shared__ float As[16][64];
    __shared__ float Bs[16][64];

    const int tid = threadIdx.x;
    const int ty = tid / 16, tx = tid % 16;
    const int a_m  = tid >> 2, a_k4 = (tid & 3) * 4;
    const int b_k  = tid >> 4, b_n4 = (tid & 15) * 4;
    const int m0 = mt * 64, n0 = nt * 64;

    float2 acc[4][2];
#pragma unroll
    for (int i = 0; i < 4; i++) { acc[i][0] = make_float2(0.f,0.f); acc[i][1] = make_float2(0.f,0.f); }

    for (int k0 = 0; k0 < D_IN; k0 += 16) {
        float4 av = make_float4(0.f,0.f,0.f,0.f);
        if (k0 + a_k4 < D_IN)
            av = *(const float4*)&X[(size_t)(m0 + a_m) * D_IN + k0 + a_k4];
        float4 bv = make_float4(0.f,0.f,0.f,0.f);
        if ((k0 + b_k < D_IN) && (n0 + b_n4 < G4))
            bv = *(const float4*)&B[(size_t)(k0 + b_k) * G4 + n0 + b_n4];

        __syncthreads();
        As[a_k4 + 0][a_m] = av.x;
        As[a_k4 + 1][a_m] = av.y;
        As[a_k4 + 2][a_m] = av.z;
        As[a_k4 + 3][a_m] = av.w;
        *(float4*)&Bs[b_k][b_n4] = bv;
        __syncthreads();

#pragma unroll
        for (int kk = 0; kk < 16; kk++) {
            float4 a4 = *(const float4*)&As[kk][ty * 4];
            float4 b4 = *(const float4*)&Bs[kk][tx * 4];
            float2 b01 = make_float2(b4.x, b4.y);
            float2 b23 = make_float2(b4.z, b4.w);
            float2 aa;
            aa = make_float2(a4.x, a4.x); acc[0][0]=ffma2(aa,b01,acc[0][0]); acc[0][1]=ffma2(aa,b23,acc[0][1]);
            aa = make_float2(a4.y, a4.y); acc[1][0]=ffma2(aa,b01,acc[1][0]); acc[1][1]=ffma2(aa,b23,acc[1][1]);
            aa = make_float2(a4.z, a4.z); acc[2][0]=ffma2(aa,b01,acc[2][0]); acc[2][1]=ffma2(aa,b23,acc[2][1]);
            aa = make_float2(a4.w, a4.w); acc[3][0]=ffma2(aa,b01,acc[3][0]); acc[3][1]=ffma2(aa,b23,acc[3][1]);
        }
    }

#pragma unroll
    for (int i = 0; i < 4; i++) {
        const int m = m0 + ty * 4 + i;
#pragma unroll
        for (int j = 0; j < 2; j++) {
            const int n = n0 + tx * 4 + j * 2;
            if (n < G4) {
                float2 v = acc[i][j];
                v.x += bias[n];
                v.y += bias[n + 1];
                *(float2*)&C[(size_t)m * G4 + n] = v;
            }
        }
    }
}

// ==================================================================
// Kernel 2 (primary): cluster LSTM, 15 CTAs x 320 threads per dir.
// Per-step protocol:
//   wait mbar[R] -> read hbuf[R] -> matvec+reduce+gates -> STS to
//   stage[s&1] -> __syncthreads -> warp0 lanes 0-14: fence.proxy.async
//   + cp.async.bulk (80 B CTA slice) to each peer's hbuf[W]+mbar[W].
// Receiver arrivals per step: 15 (one bulk per source CTA).
// ==================================================================
__global__ void __launch_bounds__(320, 1) k_lstm_cl(
    const float* __restrict__ Wr_f, const float* __restrict__ Wr_b)
{
    __shared__ __align__(16) float hbuf[2][320];         // padded 300->320
    __shared__ __align__(16) float stage[2][32];         // this CTA's 20-u slice
    __shared__ __align__(8) unsigned long long mbar[2];  // per-buffer barrier

    cg::cluster_group cl = cg::this_cluster();
    const int tid  = threadIdx.x;
    const int warp = tid >> 5, lane = tid & 31;
    const int dir  = blockIdx.x / NCTA;
    const int rank = blockIdx.x % NCTA;
    const float* __restrict__ Wr = dir ? Wr_b : Wr_f;
    const float* __restrict__ xp = g_xp[dir];
    const int u0 = rank * 20 + 2 * warp;

    // register-resident weights: w[k][g] = Wr[k*32+lane][g*300 + u0 .. +1]
    float2 w[10][4];
#pragma unroll
    for (int k = 0; k < 10; k++) {
        const int uin = k * 32 + lane;
#pragma unroll
        for (int g = 0; g < 4; g++)
            w[k][g] = (uin < U_H) ? *(const float2*)&Wr[(size_t)uin * G4 + g * 300 + u0]
                                  : make_float2(0.f, 0.f);
    }

    const uint32_t mb0 = (uint32_t)__cvta_generic_to_shared(&mbar[0]);
    const uint32_t mb1 = mb0 + 8;

    if (tid == 0) {
        asm volatile("mbarrier.init.shared.b64 [%0], %1;" :: "r"(mb0), "r"(1u));
        asm volatile("mbarrier.init.shared.b64 [%0], %1;" :: "r"(mb1), "r"(1u));
        // pre-arm phase 0 of both (15 bulk copies x 80 B = 1200 B each)
        asm volatile("mbarrier.arrive.expect_tx.shared.b64 _, [%0], %1;" :: "r"(mb0), "r"(1200u));
        asm volatile("mbarrier.arrive.expect_tx.shared.b64 _, [%0], %1;" :: "r"(mb1), "r"(1200u));
    }
    // zero h buffers (incl. padding)
    for (int i = tid; i < 640; i += 320) ((float*)hbuf)[i] = 0.f;
    __syncthreads();
    cl.sync();   // mbarriers init'd + buffers zeroed cluster-wide

    // per-lane (peer = lane) remote addresses for our slice + peer mbarriers
    uint32_t rdst0 = 0, rdst1 = 0, rmb0 = 0, rmb1 = 0;
    if (lane < NCTA) {
        const uint32_t l0 = (uint32_t)__cvta_generic_to_shared(&hbuf[0][rank * 20]);
        const uint32_t l1 = (uint32_t)__cvta_generic_to_shared(&hbuf[1][rank * 20]);
        asm("mapa.shared::cluster.u32 %0, %1, %2;" : "=r"(rdst0) : "r"(l0), "r"(lane));
        asm("mapa.shared::cluster.u32 %0, %1, %2;" : "=r"(rdst1) : "r"(l1), "r"(lane));
        asm("mapa.shared::cluster.u32 %0, %1, %2;" : "=r"(rmb0) : "r"(mb0), "r"(lane));
        asm("mapa.shared::cluster.u32 %0, %1, %2;" : "=r"(rmb1) : "r"(mb1), "r"(lane));
    }
    const uint32_t sstage0 = (uint32_t)__cvta_generic_to_shared(&stage[0][0]);
    const uint32_t sstage1 = (uint32_t)__cvta_generic_to_shared(&stage[1][0]);

    float c = 0.f;            // cell state (lanes 0,1)
    int par0 = 0, par1 = 0;   // wait-phase parity per mbarrier
    const int lb0 = lane & 1;

    for (int s = 0; s < T_SEQ; s++) {
        const int t = dir ? (T_SEQ - 1 - s) : s;
        const int R = s & 1;          // read buffer (holds h(s-1))
        const int W = R ^ 1;          // write buffer (receives h(s))

        // xp loads — depend only on s; issue before the wait
        float x0 = 0.f, x1 = 0.f, x2 = 0.f, x3 = 0.f;
        if (lane < 2) {
            const float* p = &xp[(size_t)t * G4 + u0 + lane];
            x0 = __ldg(p); x1 = __ldg(p + 300); x2 = __ldg(p + 600); x3 = __ldg(p + 900);
        }

        float gv0 = 0.f, gv1 = 0.f, gv2 = 0.f, gv3 = 0.f;
        if (s > 0) {
            const uint32_t mb = R ? mb1 : mb0;
            const int par = R ? par1 : par0;
            uint32_t done;
            do {
                asm volatile(
                    "{\n\t.reg .pred p;\n\t"
                    "mbarrier.try_wait.parity.acquire.cluster.shared::cta.b64 p, [%1], %2;\n\t"
                    "selp.b32 %0, 1, 0, p;\n\t}"
                    : "=r"(done) : "r"(mb), "r"(par) : "memory");
            } while (!done);
            if (R) par1 ^= 1; else par0 ^= 1;

            // warp0 re-arms next phase of mbar[R] (transitively precedes any
            // arrival to that phase: peers' next copies require our copies,
            // which are issued after this re-arm).
            if (warp == 0 && lane == 0)
                asm volatile("mbarrier.arrive.expect_tx.shared.b64 _, [%0], %1;"
                             :: "r"(mb), "r"(1200u));

            const float* hr = hbuf[R];
            float2 a0 = make_float2(0.f,0.f), a1 = a0, a2 = a0, a3 = a0;
#pragma unroll
            for (int k = 0; k < 10; k++) {
                const float hv = hr[k * 32 + lane];
                const float2 hh = make_float2(hv, hv);
                a0 = ffma2(hh, w[k][0], a0);
                a1 = ffma2(hh, w[k][1], a1);
                a2 = ffma2(hh, w[k][2], a2);
                a3 = ffma2(hh, w[k][3], a3);
            }

            // value-splitting reduction; column j total -> lanes (lane&7)==j
            const bool b0 = lb0;
            float k0 = b0 ? a0.y : a0.x, d0 = b0 ? a0.x : a0.y;
            float k1 = b0 ? a1.y : a1.x, d1 = b0 ? a1.x : a1.y;
            float k2 = b0 ? a2.y : a2.x, d2 = b0 ? a2.x : a2.y;
            float k3 = b0 ? a3.y : a3.x, d3 = b0 ? a3.x : a3.y;
            k0 += __shfl_xor_sync(~0u, d0, 1);
            k1 += __shfl_xor_sync(~0u, d1, 1);
            k2 += __shfl_xor_sync(~0u, d2, 1);
            k3 += __shfl_xor_sync(~0u, d3, 1);

            const bool b1 = lane & 2;
            float m0 = b1 ? k1 : k0, e0 = b1 ? k0 : k1;
            float m1 = b1 ? k3 : k2, e1 = b1 ? k2 : k3;
            m0 += __shfl_xor_sync(~0u, e0, 2);
            m1 += __shfl_xor_sync(~0u, e1, 2);

            const bool b2 = lane & 4;
            float r = b2 ? m1 : m0, f = b2 ? m0 : m1;
            r += __shfl_xor_sync(~0u, f, 4);
            r += __shfl_xor_sync(~0u, r, 8);
            r += __shfl_xor_sync(~0u, r, 16);

            gv0 = __shfl_sync(~0u, r, lb0);
            gv1 = __shfl_sync(~0u, r, 2 + lb0);
            gv2 = __shfl_sync(~0u, r, 4 + lb0);
            gv3 = __shfl_sync(~0u, r, 6 + lb0);
        }

        float hval = 0.f;
        if (lane < 2) {
            const float zi = sigm(x0 + gv0);
            const float zf = sigm(x1 + gv1);
            const float zg = sigm(x2 + gv2);
            const float zo = sigm(x3 + gv3);
            c = zf * c + zi * zg;
            hval = zo * sigm(c);
        }
        const float h0 = __shfl_sync(~0u, hval, 0);
        const float h1 = __shfl_sync(~0u, hval, 1);

        // stage this warp's pair locally (double-buffered by step parity)
        if (lane == 0)
            *(float2*)&stage[s & 1][2 * warp] = make_float2(h0, h1);

        __syncthreads();   // all 10 warps staged

        // warp0 publishes the CTA slice: one 80 B bulk copy per peer
        if (s + 1 < T_SEQ && warp == 0 && lane < NCTA) {
            asm volatile("fence.proxy.async.shared::cta;" ::: "memory");
            const uint32_t dst = W ? rdst1 : rdst0;
            const uint32_t rmb = W ? rmb1 : rmb0;
            const uint32_t src = (s & 1) ? sstage1 : sstage0;
            asm volatile(
                "cp.async.bulk.shared::cluster.shared::cta.mbarrier::complete_tx::bytes "
                "[%0], [%1], %2, [%3];"
                :: "r"(dst), "r"(src), "r"(80u), "r"(rmb) : "memory");
        }

        if (lane == 0)
            *(float2*)&g_H[(size_t)t * 600 + dir * 300 + u0] = make_float2(h0, h1);
    }
}

// ==================================================================
// Kernel 2 (fallback): global-flag LSTM (no cluster), hot spin.
// ==================================================================
__global__ void __launch_bounds__(480, 1) k_lstm(
    const float* __restrict__ Wr_f, const float* __restrict__ Wr_b)
{
    const int tid  = threadIdx.x;
    const int warp = tid >> 5, lane = tid & 31;
    const int dir  = blockIdx.x / 10;
    const int rank = blockIdx.x % 10;
    const float* __restrict__ Wr = dir ? Wr_b : Wr_f;
    const float* __restrict__ xp = g_xp[dir];
    const int u0 = rank * 30 + 2 * warp;

    float2 w[10][4];
#pragma unroll
    for (int k = 0; k < 10; k++) {
        const int uin = k * 32 + lane;
#pragma unroll
        for (int g = 0; g < 4; g++)
            w[k][g] = (uin < U_H) ? *(const float2*)&Wr[(size_t)uin * G4 + g * 300 + u0]
                                  : make_float2(0.f, 0.f);
    }

    float c = 0.f;

    for (int s = 0; s < T_SEQ; s++) {
        const int t = dir ? (T_SEQ - 1 - s) : s;

        float x0 = 0.f, x1 = 0.f, x2 = 0.f, x3 = 0.f;
        if (lane < 2) {
            const float* p = &xp[(size_t)t * G4 + u0 + lane];
            x0 = __ldg(p); x1 = __ldg(p + 300); x2 = __ldg(p + 600); x3 = __ldg(p + 900);
        }

        float2 a0 = make_float2(0.f,0.f), a1 = a0, a2 = a0, a3 = a0;
        if (s > 0) {
            if (warp == 0 && lane < 10) {
                int v;
                const int* fp = &g_flag[dir][lane];
                do {
                    asm volatile("ld.acquire.gpu.s32 %0, [%1];" : "=r"(v) : "l"(fp));
                } while (v < s);
            }
            __syncthreads();

            const int tp = dir ? (t + 1) : (t - 1);
            const float* hrow = &g_H[(size_t)tp * 600 + dir * 300];
            float hv[10];
#pragma unroll
            for (int k = 0; k < 10; k++) {
                const int uin = k * 32 + lane;
                hv[k] = (uin < U_H) ? __ldcg(&hrow[uin]) : 0.f;
            }
#pragma unroll
            for (int k = 0; k < 10; k++) {
                const float2 hh = make_float2(hv[k], hv[k]);
                a0 = ffma2(hh, w[k][0], a0);
                a1 = ffma2(hh, w[k][1], a1);
                a2 = ffma2(hh, w[k][2], a2);
                a3 = ffma2(hh, w[k][3], a3);
            }
#pragma unroll
            for (int off = 16; off > 0; off >>= 1) {
                a0.x += __shfl_xor_sync(~0u, a0.x, off); a0.y += __shfl_xor_sync(~0u, a0.y, off);
                a1.x += __shfl_xor_sync(~0u, a1.x, off); a1.y += __shfl_xor_sync(~0u, a1.y, off);
                a2.x += __shfl_xor_sync(~0u, a2.x, off); a2.y += __shfl_xor_sync(~0u, a2.y, off);
                a3.x += __shfl_xor_sync(~0u, a3.x, off); a3.y += __shfl_xor_sync(~0u, a3.y, off);
            }
        }

        float hval = 0.f;
        if (lane < 2) {
            const float zi = sigm(x0 + (lane ? a0.y : a0.x));
            const float zf = sigm(x1 + (lane ? a1.y : a1.x));
            const float zg = sigm(x2 + (lane ? a2.y : a2.x));
            const float zo = sigm(x3 + (lane ? a3.y : a3.x));
            c = zf * c + zi * zg;
            hval = zo * sigm(c);
        }
        const float h0 = __shfl_sync(~0u, hval, 0);
        const float h1 = __shfl_sync(~0u, hval, 1);
        if (lane == 0)
            *(float2*)&g_H[(size_t)t * 600 + dir * 300 + u0] = make_float2(h0, h1);

        __syncthreads();
        if (tid == 0) {
            asm volatile("st.release.gpu.s32 [%0], %1;"
                         :: "l"(&g_flag[dir][rank]), "r"(s + 1) : "memory");
        }
    }
}

// ==================================================================
// Kernel 3: L = W2 @ tanh(W1 @ H^T)  (30 x T), fused.
// ==================================================================
#define TI 8
__global__ void __launch_bounds__(512) k_logits(
    const float* __restrict__ W1, const float* __restrict__ W2)
{
    __shared__ float Hs[600][TI];
    __shared__ float vs[ADIM][TI + 1];

    const int tid = threadIdx.x, lane = tid & 31, warp = tid >> 5;
    const int tchunk = blockIdx.x;

    for (int g = 0; g < 16; g++) {
        const int t0 = tchunk * 128 + g * TI;

        for (int i = tid; i < 600 * TI; i += 512) {
            const int tt = i / 600, k = i % 600;
            Hs[k][tt] = g_H[(size_t)(t0 + tt) * 600 + k];
        }
        __syncthreads();

        if (tid < ADIM) {
            float acc[TI];
#pragma unroll
            for (int q = 0; q < TI; q++) acc[q] = 0.f;
            const float* wrow = &W1[(size_t)tid * 600];
            for (int k = 0; k < 600; k++) {
                const float wv = __ldg(&wrow[k]);
                const float4 ha = *(const float4*)&Hs[k][0];
                const float4 hb = *(const float4*)&Hs[k][4];
                acc[0] += wv * ha.x; acc[1] += wv * ha.y;
                acc[2] += wv * ha.z; acc[3] += wv * ha.w;
                acc[4] += wv * hb.x; acc[5] += wv * hb.y;
                acc[6] += wv * hb.z; acc[7] += wv * hb.w;
            }
#pragma unroll
            for (int q = 0; q < TI; q++) vs[tid][q] = tanhf(acc[q]);
        }
        __syncthreads();

        for (int r = warp; r < R_ROWS; r += 16) {
            float acc[TI];
#pragma unroll
            for (int q = 0; q < TI; q++) acc[q] = 0.f;
            for (int a = lane; a < ADIM; a += 32) {
                const float wv = __ldg(&W2[(size_t)r * ADIM + a]);
#pragma unroll
                for (int q = 0; q < TI; q++) acc[q] += wv * vs[a][q];
            }
#pragma unroll
            for (int q = 0; q < TI; q++) {
#pragma unroll
                for (int off = 16; off > 0; off >>= 1)
                    acc[q] += __shfl_xor_sync(~0u, acc[q], off);
            }
            if (lane == 0) {
#pragma unroll
                for (int q = 0; q < TI; q++)
                    g_L[(size_t)r * T_SEQ + t0 + q] = acc[q];
            }
        }
        __syncthreads();
    }
}

// ==================================================================
// Kernel 4: p[t] = H[t,:] . dense_w ; also zero the scalar accumulator.
// ==================================================================
__global__ void __launch_bounds__(256) k_p(const float* __restrict__ dw)
{
    if (blockIdx.x == 0 && threadIdx.x == 0) g_acc = 0.f;
    const int warp = threadIdx.x >> 5, lane = threadIdx.x & 31;
    const int t = blockIdx.x * 8 + warp;
    float s = 0.f;
    const float* h = &g_H[(size_t)t * 600];
    for (int k = lane; k < 600; k += 32) s += h[k] * __ldg(&dw[k]);
#pragma unroll
    for (int o = 16; o > 0; o >>= 1) s += __shfl_xor_sync(~0u, s, o);
    if (lane == 0) g_p[t] = s;
}

// ==================================================================
// Kernel 5: per attention row r: softmax over T; accumulate A_r . p.
// ==================================================================
__global__ void __launch_bounds__(256) k_softmax_acc()
{
    const int r = blockIdx.x, tid = threadIdx.x;
    __shared__ float red[256];
    const float* L = &g_L[(size_t)r * T_SEQ];

    float m = -1e30f;
    for (int i = tid; i < T_SEQ; i += 256) m = fmaxf(m, L[i]);
    red[tid] = m; __syncthreads();
    for (int o = 128; o > 0; o >>= 1) {
        if (tid < o) red[tid] = fmaxf(red[tid], red[tid + o]);
        __syncthreads();
    }
    m = red[0]; __syncthreads();

    float se = 0.f, sp = 0.f;
    for (int i = tid; i < T_SEQ; i += 256) {
        const float e = __expf(L[i] - m);
        se += e;
        sp += e * g_p[i];
    }
    red[tid] = se; __syncthreads();
    for (int o = 128; o > 0; o >>= 1) {
        if (tid < o) red[tid] += red[tid + o];
        __syncthreads();
    }
    se = red[0]; __syncthreads();

    red[tid] = sp; __syncthreads();
    for (int o = 128; o > 0; o >>= 1) {
        if (tid < o) red[tid] += red[tid + o];
        __syncthreads();
    }
    if (tid == 0) atomicAdd(&g_acc, red[0] / se);
}

// ==================================================================
// Kernel 6: final scalar.
// ==================================================================
__global__ void k_final(const float* __restrict__ db, float* __restrict__ out)
{
    const float v = g_acc / 30.f + db[0];
    out[0] = 1.f / (1.f + expf(-v));
}

// ==================================================================
extern "C" void kernel_launch(void* const* d_in, const int* in_sizes, int n_in,
                              void* d_out, int out_size)
{
    const float* emb  = (const float*)d_in[0];
    const float* Wk_f = (const float*)d_in[1];
    const float* Wr_f = (const float*)d_in[2];
    const float* b_f  = (const float*)d_in[3];
    const float* Wk_b = (const float*)d_in[4];
    const float* Wr_b = (const float*)d_in[5];
    const float* b_b  = (const float*)d_in[6];
    const float* W1   = (const float*)d_in[7];
    const float* W2   = (const float*)d_in[8];
    const float* dw   = (const float*)d_in[9];
    const float* db   = (const float*)d_in[10];
    float* out = (float*)d_out;

    k_gemm_xp<<<dim3(19, 256, 2), 256>>>(emb, Wk_f, b_f, Wk_b, b_b);

    // Primary: cluster(NCTA) LSTM. Deterministic fallback if unsupported.
    cudaError_t e = cudaFuncSetAttribute(
        k_lstm_cl, cudaFuncAttributeNonPortableClusterSizeAllowed, 1);
    bool launched = false;
    if (e == cudaSuccess) {
        cudaLaunchConfig_t cfg = {};
        cfg.gridDim  = dim3(2 * NCTA, 1, 1);
        cfg.blockDim = dim3(320, 1, 1);
        cfg.dynamicSmemBytes = 0;
        cfg.stream = 0;
        cudaLaunchAttribute attrs[1];
        attrs[0].id = cudaLaunchAttributeClusterDimension;
        attrs[0].val.clusterDim.x = NCTA;
        attrs[0].val.clusterDim.y = 1;
        attrs[0].val.clusterDim.z = 1;
        cfg.attrs = attrs;
        cfg.numAttrs = 1;
        e = cudaLaunchKernelEx(&cfg, k_lstm_cl, Wr_f, Wr_b);
        launched = (e == cudaSuccess);
    }
    if (!launched) {
        cudaGetLastError();   // clear error state
        k_lstm<<<20, 480>>>(Wr_f, Wr_b);
    }

    k_logits<<<128, 512>>>(W1, W2);
    k_p<<<2048, 256>>>(dw);
    k_softmax_acc<<<30, 256>>>();
    k_final<<<1, 1>>>(db, out);
}

// round 13
// speedup vs baseline: 4.4533x; 1.2152x over previous
#include <cuda_runtime.h>
#include <cuda_bf16.h>
#include <cooperative_groups.h>
#include <cstdint>

namespace cg = cooperative_groups;

#define T_SEQ 16384
#define D_IN  300
#define U_H   300
#define G4    1200
#define ADIM  350
#define R_ROWS 30
#define NCTA  15     // CTAs per direction (cluster size)

// ---------------- device scratch ----------------
__device__ float g_xp[2][(size_t)T_SEQ * G4];   // per-direction x@Wk+b
__device__ float g_H[(size_t)T_SEQ * 600];      // [hf | hb] per t
__device__ float g_L[(size_t)R_ROWS * T_SEQ];   // attention logits
__device__ float g_p[T_SEQ];                    // H[t] . dense_w
__device__ float g_acc;                         // sum over rows of (A_r . p)
__device__ int   g_flag[2][16];                 // per-(dir,rank) step flags (fallback path)

// ---------------- helpers ----------------
__device__ __forceinline__ float2 ffma2(float2 a, float2 b, float2 c) {
    union Cv { float2 f; unsigned long long u; };
    Cv ua, ub, uc, ud;
    ua.f = a; ub.f = b; uc.f = c;
    asm("fma.rn.f32x2 %0, %1, %2, %3;" : "=l"(ud.u) : "l"(ua.u), "l"(ub.u), "l"(uc.u));
    return ud.f;
}
__device__ __forceinline__ float sigm(float x) { return 1.0f / (1.0f + __expf(-x)); }

// ==================================================================
// Kernel 1: xp = x @ Wk + b for both directions (blockIdx.z selects).
// ==================================================================
__global__ void __launch_bounds__(256) k_gemm_xp(
    const float* __restrict__ X,
    const float* __restrict__ Wf, const float* __restrict__ bf,
    const float* __restrict__ Wb, const float* __restrict__ bb)
{
    if (blockIdx.x == 0 && blockIdx.y == 0 && blockIdx.z == 0 && threadIdx.x < 32) {
        g_flag[0][threadIdx.x % 16] = 0;
        g_flag[1][threadIdx.x % 16] = 0;
    }
    const int nt = blockIdx.x, mt = blockIdx.y, wsel = blockIdx.z;
    const float* B    = wsel ? Wb : Wf;
    const float* bias = wsel ? bb : bf;
    float* C = g_xp[wsel];

    __shared__ float As[16][64];
    __shared__ float Bs[16][64];

    const int tid = threadIdx.x;
    const int ty = tid / 16, tx = tid % 16;
    const int a_m  = tid >> 2, a_k4 = (tid & 3) * 4;
    const int b_k  = tid >> 4, b_n4 = (tid & 15) * 4;
    const int m0 = mt * 64, n0 = nt * 64;

    float2 acc[4][2];
#pragma unroll
    for (int i = 0; i < 4; i++) { acc[i][0] = make_float2(0.f,0.f); acc[i][1] = make_float2(0.f,0.f); }

    for (int k0 = 0; k0 < D_IN; k0 += 16) {
        float4 av = make_float4(0.f,0.f,0.f,0.f);
        if (k0 + a_k4 < D_IN)
            av = *(const float4*)&X[(size_t)(m0 + a_m) * D_IN + k0 + a_k4];
        float4 bv = make_float4(0.f,0.f,0.f,0.f);
        if ((k0 + b_k < D_IN) && (n0 + b_n4 < G4))
            bv = *(const float4*)&B[(size_t)(k0 + b_k) * G4 + n0 + b_n4];

        __syncthreads();
        As[a_k4 + 0][a_m] = av.x;
        As[a_k4 + 1][a_m] = av.y;
        As[a_k4 + 2][a_m] = av.z;
        As[a_k4 + 3][a_m] = av.w;
        *(float4*)&Bs[b_k][b_n4] = bv;
        __syncthreads();

#pragma unroll
        for (int kk = 0; kk < 16; kk++) {
            float4 a4 = *(const float4*)&As[kk][ty * 4];
            float4 b4 = *(const float4*)&Bs[kk][tx * 4];
            float2 b01 = make_float2(b4.x, b4.y);
            float2 b23 = make_float2(b4.z, b4.w);
            float2 aa;
            aa = make_float2(a4.x, a4.x); acc[0][0]=ffma2(aa,b01,acc[0][0]); acc[0][1]=ffma2(aa,b23,acc[0][1]);
            aa = make_float2(a4.y, a4.y); acc[1][0]=ffma2(aa,b01,acc[1][0]); acc[1][1]=ffma2(aa,b23,acc[1][1]);
            aa = make_float2(a4.z, a4.z); acc[2][0]=ffma2(aa,b01,acc[2][0]); acc[2][1]=ffma2(aa,b23,acc[2][1]);
            aa = make_float2(a4.w, a4.w); acc[3][0]=ffma2(aa,b01,acc[3][0]); acc[3][1]=ffma2(aa,b23,acc[3][1]);
        }
    }

#pragma unroll
    for (int i = 0; i < 4; i++) {
        const int m = m0 + ty * 4 + i;
#pragma unroll
        for (int j = 0; j < 2; j++) {
            const int n = n0 + tx * 4 + j * 2;
            if (n < G4) {
                float2 v = acc[i][j];
                v.x += bias[n];
                v.y += bias[n + 1];
                *(float2*)&C[(size_t)m * G4 + n] = v;
            }
        }
    }
}

// ==================================================================
// Kernel 2 (primary): cluster LSTM, 15 CTAs x 320 threads per dir.
// R10 core (per-warp st.async, 150 arrivals, double-buffered mbar)
// + xp software pipelining (prefetch next step) + suspend-hint wait.
// ==================================================================
__global__ void __launch_bounds__(320, 1) k_lstm_cl(
    const float* __restrict__ Wr_f, const float* __restrict__ Wr_b)
{
    __shared__ float hbuf[2][320];                       // padded 300->320
    __shared__ __align__(8) unsigned long long mbar[2];  // per-buffer barrier

    cg::cluster_group cl = cg::this_cluster();
    const int tid  = threadIdx.x;
    const int warp = tid >> 5, lane = tid & 31;
    const int dir  = blockIdx.x / NCTA;
    const int rank = blockIdx.x % NCTA;
    const float* __restrict__ Wr = dir ? Wr_b : Wr_f;
    const float* __restrict__ xp = g_xp[dir];
    const int u0 = rank * 20 + 2 * warp;

    // register-resident weights: w[k][g] = Wr[k*32+lane][g*300 + u0 .. +1]
    float2 w[10][4];
#pragma unroll
    for (int k = 0; k < 10; k++) {
        const int uin = k * 32 + lane;
#pragma unroll
        for (int g = 0; g < 4; g++)
            w[k][g] = (uin < U_H) ? *(const float2*)&Wr[(size_t)uin * G4 + g * 300 + u0]
                                  : make_float2(0.f, 0.f);
    }

    const uint32_t mb0 = (uint32_t)__cvta_generic_to_shared(&mbar[0]);
    const uint32_t mb1 = mb0 + 8;

    if (tid == 0) {
        asm volatile("mbarrier.init.shared.b64 [%0], %1;" :: "r"(mb0), "r"(1u));
        asm volatile("mbarrier.init.shared.b64 [%0], %1;" :: "r"(mb1), "r"(1u));
        // pre-arm phase-0 expects: 150 warp-pairs x 8 B = 1200 B each
        asm volatile("mbarrier.arrive.expect_tx.shared.b64 _, [%0], %1;" :: "r"(mb0), "r"(1200u));
        asm volatile("mbarrier.arrive.expect_tx.shared.b64 _, [%0], %1;" :: "r"(mb1), "r"(1200u));
    }
    for (int i = tid; i < 640; i += 320) ((float*)hbuf)[i] = 0.f;
    __syncthreads();
    cl.sync();   // all CTAs: mbarriers init'd + buffers zeroed before any store

    // remote addresses for this warp's pair in peer rank = lane (lane<NCTA)
    uint32_t rh0 = 0, rh1 = 0, rm0 = 0, rm1 = 0;
    if (lane < NCTA) {
        const uint32_t lh0 = (uint32_t)__cvta_generic_to_shared(&hbuf[0][u0]);
        const uint32_t lh1 = (uint32_t)__cvta_generic_to_shared(&hbuf[1][u0]);
        asm("mapa.shared::cluster.u32 %0, %1, %2;" : "=r"(rh0) : "r"(lh0), "r"(lane));
        asm("mapa.shared::cluster.u32 %0, %1, %2;" : "=r"(rh1) : "r"(lh1), "r"(lane));
        asm("mapa.shared::cluster.u32 %0, %1, %2;" : "=r"(rm0) : "r"(mb0), "r"(lane));
        asm("mapa.shared::cluster.u32 %0, %1, %2;" : "=r"(rm1) : "r"(mb1), "r"(lane));
    }

    float c = 0.f;            // cell state (lanes 0,1)
    int par0 = 0, par1 = 0;   // phase parity per mbarrier
    const int lb0 = lane & 1;

    // prime xp pipeline: load step 0's values
    float xc0 = 0.f, xc1 = 0.f, xc2 = 0.f, xc3 = 0.f;
    if (lane < 2) {
        const int t0 = dir ? (T_SEQ - 1) : 0;
        const float* p = &xp[(size_t)t0 * G4 + u0 + lane];
        xc0 = __ldg(p); xc1 = __ldg(p + 300); xc2 = __ldg(p + 600); xc3 = __ldg(p + 900);
    }

    for (int s = 0; s < T_SEQ; s++) {
        const int t   = dir ? (T_SEQ - 1 - s) : s;
        const int cur = s & 1;

        // prefetch next step's xp — a full step of latency overlap
        float xn0 = 0.f, xn1 = 0.f, xn2 = 0.f, xn3 = 0.f;
        if (s + 1 < T_SEQ && lane < 2) {
            const int tn = dir ? (t - 1) : (t + 1);
            const float* p = &xp[(size_t)tn * G4 + u0 + lane];
            xn0 = __ldg(p); xn1 = __ldg(p + 300); xn2 = __ldg(p + 600); xn3 = __ldg(p + 900);
        }

        float gv0 = 0.f, gv1 = 0.f, gv2 = 0.f, gv3 = 0.f;
        if (s > 0) {
            const uint32_t mb = cur ? mb1 : mb0;
            const int par = cur ? par1 : par0;
            // wait for all 150 h-pairs of step s-1; suspend-hint = HW sleep
            uint32_t done;
            do {
                asm volatile(
                    "{\n\t.reg .pred p;\n\t"
                    "mbarrier.try_wait.parity.acquire.cluster.shared::cta.b64 p, [%1], %2, 0x989680;\n\t"
                    "selp.b32 %0, 1, 0, p;\n\t}"
                    : "=r"(done) : "r"(mb), "r"(par) : "memory");
            } while (!done);
            if (cur) par1 ^= 1; else par0 ^= 1;

            // warp0 re-arms next phase BEFORE its own stores (transitively safe)
            if (warp == 0 && lane == 0)
                asm volatile("mbarrier.arrive.expect_tx.shared.b64 _, [%0], %1;"
                             :: "r"(mb), "r"(1200u));

            const float* hr = hbuf[cur];
            float2 a0 = make_float2(0.f,0.f), a1 = a0, a2 = a0, a3 = a0;
#pragma unroll
            for (int k = 0; k < 10; k++) {
                const float hv = hr[k * 32 + lane];
                const float2 hh = make_float2(hv, hv);
                a0 = ffma2(hh, w[k][0], a0);
                a1 = ffma2(hh, w[k][1], a1);
                a2 = ffma2(hh, w[k][2], a2);
                a3 = ffma2(hh, w[k][3], a3);
            }

            // value-splitting reduction: column j total lands in lanes with
            // (lane&7)==j; then 4 idx-shuffles gather the per-u gate totals.
            const bool b0 = lb0;
            float k0 = b0 ? a0.y : a0.x, d0 = b0 ? a0.x : a0.y;
            float k1 = b0 ? a1.y : a1.x, d1 = b0 ? a1.x : a1.y;
            float k2 = b0 ? a2.y : a2.x, d2 = b0 ? a2.x : a2.y;
            float k3 = b0 ? a3.y : a3.x, d3 = b0 ? a3.x : a3.y;
            k0 += __shfl_xor_sync(~0u, d0, 1);
            k1 += __shfl_xor_sync(~0u, d1, 1);
            k2 += __shfl_xor_sync(~0u, d2, 1);
            k3 += __shfl_xor_sync(~0u, d3, 1);

            const bool b1 = lane & 2;
            float m0 = b1 ? k1 : k0, e0 = b1 ? k0 : k1;
            float m1 = b1 ? k3 : k2, e1 = b1 ? k2 : k3;
            m0 += __shfl_xor_sync(~0u, e0, 2);
            m1 += __shfl_xor_sync(~0u, e1, 2);

            const bool b2 = lane & 4;
            float r = b2 ? m1 : m0, f = b2 ? m0 : m1;
            r += __shfl_xor_sync(~0u, f, 4);
            r += __shfl_xor_sync(~0u, r, 8);
            r += __shfl_xor_sync(~0u, r, 16);

            gv0 = __shfl_sync(~0u, r, lb0);
            gv1 = __shfl_sync(~0u, r, 2 + lb0);
            gv2 = __shfl_sync(~0u, r, 4 + lb0);
            gv3 = __shfl_sync(~0u, r, 6 + lb0);
        }

        float hval = 0.f;
        if (lane < 2) {
            const float zi = sigm(xc0 + gv0);
            const float zf = sigm(xc1 + gv1);
            const float zg = sigm(xc2 + gv2);
            const float zo = sigm(xc3 + gv3);
            c = zf * c + zi * zg;
            hval = zo * sigm(c);
        }
        const float h0 = __shfl_sync(~0u, hval, 0);
        const float h1 = __shfl_sync(~0u, hval, 1);

        // publish h(s) into every CTA's next buffer + credit its mbarrier
        if (s + 1 < T_SEQ && lane < NCTA) {
            const uint32_t rh = cur ? rh0 : rh1;   // nxt = cur^1
            const uint32_t rm = cur ? rm0 : rm1;
            asm volatile(
                "st.async.shared::cluster.mbarrier::complete_tx::bytes.v2.f32 "
                "[%0], {%1, %2}, [%3];"
                :: "r"(rh), "f"(h0), "f"(h1), "r"(rm) : "memory");
        }

        if (lane == 0)
            *(float2*)&g_H[(size_t)t * 600 + dir * 300 + u0] = make_float2(h0, h1);

        // rotate xp pipeline
        xc0 = xn0; xc1 = xn1; xc2 = xn2; xc3 = xn3;
    }
}

// ==================================================================
// Kernel 2 (fallback): global-flag LSTM (no cluster), hot spin.
// ==================================================================
__global__ void __launch_bounds__(480, 1) k_lstm(
    const float* __restrict__ Wr_f, const float* __restrict__ Wr_b)
{
    const int tid  = threadIdx.x;
    const int warp = tid >> 5, lane = tid & 31;
    const int dir  = blockIdx.x / 10;
    const int rank = blockIdx.x % 10;
    const float* __restrict__ Wr = dir ? Wr_b : Wr_f;
    const float* __restrict__ xp = g_xp[dir];
    const int u0 = rank * 30 + 2 * warp;

    float2 w[10][4];
#pragma unroll
    for (int k = 0; k < 10; k++) {
        const int uin = k * 32 + lane;
#pragma unroll
        for (int g = 0; g < 4; g++)
            w[k][g] = (uin < U_H) ? *(const float2*)&Wr[(size_t)uin * G4 + g * 300 + u0]
                                  : make_float2(0.f, 0.f);
    }

    float c = 0.f;

    for (int s = 0; s < T_SEQ; s++) {
        const int t = dir ? (T_SEQ - 1 - s) : s;

        float x0 = 0.f, x1 = 0.f, x2 = 0.f, x3 = 0.f;
        if (lane < 2) {
            const float* p = &xp[(size_t)t * G4 + u0 + lane];
            x0 = __ldg(p); x1 = __ldg(p + 300); x2 = __ldg(p + 600); x3 = __ldg(p + 900);
        }

        float2 a0 = make_float2(0.f,0.f), a1 = a0, a2 = a0, a3 = a0;
        if (s > 0) {
            if (warp == 0 && lane < 10) {
                int v;
                const int* fp = &g_flag[dir][lane];
                do {
                    asm volatile("ld.acquire.gpu.s32 %0, [%1];" : "=r"(v) : "l"(fp));
                } while (v < s);
            }
            __syncthreads();

            const int tp = dir ? (t + 1) : (t - 1);
            const float* hrow = &g_H[(size_t)tp * 600 + dir * 300];
            float hv[10];
#pragma unroll
            for (int k = 0; k < 10; k++) {
                const int uin = k * 32 + lane;
                hv[k] = (uin < U_H) ? __ldcg(&hrow[uin]) : 0.f;
            }
#pragma unroll
            for (int k = 0; k < 10; k++) {
                const float2 hh = make_float2(hv[k], hv[k]);
                a0 = ffma2(hh, w[k][0], a0);
                a1 = ffma2(hh, w[k][1], a1);
                a2 = ffma2(hh, w[k][2], a2);
                a3 = ffma2(hh, w[k][3], a3);
            }
#pragma unroll
            for (int off = 16; off > 0; off >>= 1) {
                a0.x += __shfl_xor_sync(~0u, a0.x, off); a0.y += __shfl_xor_sync(~0u, a0.y, off);
                a1.x += __shfl_xor_sync(~0u, a1.x, off); a1.y += __shfl_xor_sync(~0u, a1.y, off);
                a2.x += __shfl_xor_sync(~0u, a2.x, off); a2.y += __shfl_xor_sync(~0u, a2.y, off);
                a3.x += __shfl_xor_sync(~0u, a3.x, off); a3.y += __shfl_xor_sync(~0u, a3.y, off);
            }
        }

        float hval = 0.f;
        if (lane < 2) {
            const float zi = sigm(x0 + (lane ? a0.y : a0.x));
            const float zf = sigm(x1 + (lane ? a1.y : a1.x));
            const float zg = sigm(x2 + (lane ? a2.y : a2.x));
            const float zo = sigm(x3 + (lane ? a3.y : a3.x));
            c = zf * c + zi * zg;
            hval = zo * sigm(c);
        }
        const float h0 = __shfl_sync(~0u, hval, 0);
        const float h1 = __shfl_sync(~0u, hval, 1);
        if (lane == 0)
            *(float2*)&g_H[(size_t)t * 600 + dir * 300 + u0] = make_float2(h0, h1);

        __syncthreads();
        if (tid == 0) {
            asm volatile("st.release.gpu.s32 [%0], %1;"
                         :: "l"(&g_flag[dir][rank]), "r"(s + 1) : "memory");
        }
    }
}

// ==================================================================
// Kernel 3: L = W2 @ tanh(W1 @ H^T)  (30 x T), fused.
// ==================================================================
#define TI 8
__global__ void __launch_bounds__(512) k_logits(
    const float* __restrict__ W1, const float* __restrict__ W2)
{
    __shared__ float Hs[600][TI];
    __shared__ float vs[ADIM][TI + 1];

    const int tid = threadIdx.x, lane = tid & 31, warp = tid >> 5;
    const int tchunk = blockIdx.x;

    for (int g = 0; g < 16; g++) {
        const int t0 = tchunk * 128 + g * TI;

        for (int i = tid; i < 600 * TI; i += 512) {
            const int tt = i / 600, k = i % 600;
            Hs[k][tt] = g_H[(size_t)(t0 + tt) * 600 + k];
        }
        __syncthreads();

        if (tid < ADIM) {
            float acc[TI];
#pragma unroll
            for (int q = 0; q < TI; q++) acc[q] = 0.f;
            const float* wrow = &W1[(size_t)tid * 600];
            for (int k = 0; k < 600; k++) {
                const float wv = __ldg(&wrow[k]);
                const float4 ha = *(const float4*)&Hs[k][0];
                const float4 hb = *(const float4*)&Hs[k][4];
                acc[0] += wv * ha.x; acc[1] += wv * ha.y;
                acc[2] += wv * ha.z; acc[3] += wv * ha.w;
                acc[4] += wv * hb.x; acc[5] += wv * hb.y;
                acc[6] += wv * hb.z; acc[7] += wv * hb.w;
            }
#pragma unroll
            for (int q = 0; q < TI; q++) vs[tid][q] = tanhf(acc[q]);
        }
        __syncthreads();

        for (int r = warp; r < R_ROWS; r += 16) {
            float acc[TI];
#pragma unroll
            for (int q = 0; q < TI; q++) acc[q] = 0.f;
            for (int a = lane; a < ADIM; a += 32) {
                const float wv = __ldg(&W2[(size_t)r * ADIM + a]);
#pragma unroll
                for (int q = 0; q < TI; q++) acc[q] += wv * vs[a][q];
            }
#pragma unroll
            for (int q = 0; q < TI; q++) {
#pragma unroll
                for (int off = 16; off > 0; off >>= 1)
                    acc[q] += __shfl_xor_sync(~0u, acc[q], off);
            }
            if (lane == 0) {
#pragma unroll
                for (int q = 0; q < TI; q++)
                    g_L[(size_t)r * T_SEQ + t0 + q] = acc[q];
            }
        }
        __syncthreads();
    }
}

// ==================================================================
// Kernel 4: p[t] = H[t,:] . dense_w ; also zero the scalar accumulator.
// ==================================================================
__global__ void __launch_bounds__(256) k_p(const float* __restrict__ dw)
{
    if (blockIdx.x == 0 && threadIdx.x == 0) g_acc = 0.f;
    const int warp = threadIdx.x >> 5, lane = threadIdx.x & 31;
    const int t = blockIdx.x * 8 + warp;
    float s = 0.f;
    const float* h = &g_H[(size_t)t * 600];
    for (int k = lane; k < 600; k += 32) s += h[k] * __ldg(&dw[k]);
#pragma unroll
    for (int o = 16; o > 0; o >>= 1) s += __shfl_xor_sync(~0u, s, o);
    if (lane == 0) g_p[t] = s;
}

// ==================================================================
// Kernel 5: per attention row r: softmax over T; accumulate A_r . p.
// ==================================================================
__global__ void __launch_bounds__(256) k_softmax_acc()
{
    const int r = blockIdx.x, tid = threadIdx.x;
    __shared__ float red[256];
    const float* L = &g_L[(size_t)r * T_SEQ];

    float m = -1e30f;
    for (int i = tid; i < T_SEQ; i += 256) m = fmaxf(m, L[i]);
    red[tid] = m; __syncthreads();
    for (int o = 128; o > 0; o >>= 1) {
        if (tid < o) red[tid] = fmaxf(red[tid], red[tid + o]);
        __syncthreads();
    }
    m = red[0]; __syncthreads();

    float se = 0.f, sp = 0.f;
    for (int i = tid; i < T_SEQ; i += 256) {
        const float e = __expf(L[i] - m);
        se += e;
        sp += e * g_p[i];
    }
    red[tid] = se; __syncthreads();
    for (int o = 128; o > 0; o >>= 1) {
        if (tid < o) red[tid] += red[tid + o];
        __syncthreads();
    }
    se = red[0]; __syncthreads();

    red[tid] = sp; __syncthreads();
    for (int o = 128; o > 0; o >>= 1) {
        if (tid < o) red[tid] += red[tid + o];
        __syncthreads();
    }
    if (tid == 0) atomicAdd(&g_acc, red[0] / se);
}

// ==================================================================
// Kernel 6: final scalar.
// ==================================================================
__global__ void k_final(const float* __restrict__ db, float* __restrict__ out)
{
    const float v = g_acc / 30.f + db[0];
    out[0] = 1.f / (1.f + expf(-v));
}

// ==================================================================
extern "C" void kernel_launch(void* const* d_in, const int* in_sizes, int n_in,
                              void* d_out, int out_size)
{
    const float* emb  = (const float*)d_in[0];
    const float* Wk_f = (const float*)d_in[1];
    const float* Wr_f = (const float*)d_in[2];
    const float* b_f  = (const float*)d_in[3];
    const float* Wk_b = (const float*)d_in[4];
    const float* Wr_b = (const float*)d_in[5];
    const float* b_b  = (const float*)d_in[6];
    const float* W1   = (const float*)d_in[7];
    const float* W2   = (const float*)d_in[8];
    const float* dw   = (const float*)d_in[9];
    const float* db   = (const float*)d_in[10];
    float* out = (float*)d_out;

    k_gemm_xp<<<dim3(19, 256, 2), 256>>>(emb, Wk_f, b_f, Wk_b, b_b);

    // Primary: cluster(NCTA) LSTM. Deterministic fallback if unsupported.
    cudaError_t e = cudaFuncSetAttribute(
        k_lstm_cl, cudaFuncAttributeNonPortableClusterSizeAllowed, 1);
    bool launched = false;
    if (e == cudaSuccess) {
        cudaLaunchConfig_t cfg = {};
        cfg.gridDim  = dim3(2 * NCTA, 1, 1);
        cfg.blockDim = dim3(320, 1, 1);
        cfg.dynamicSmemBytes = 0;
        cfg.stream = 0;
        cudaLaunchAttribute attrs[1];
        attrs[0].id = cudaLaunchAttributeClusterDimension;
        attrs[0].val.clusterDim.x = NCTA;
        attrs[0].val.clusterDim.y = 1;
        attrs[0].val.clusterDim.z = 1;
        cfg.attrs = attrs;
        cfg.numAttrs = 1;
        e = cudaLaunchKernelEx(&cfg, k_lstm_cl, Wr_f, Wr_b);
        launched = (e == cudaSuccess);
    }
    if (!launched) {
        cudaGetLastError();   // clear error state
        k_lstm<<<20, 480>>>(Wr_f, Wr_b);
    }

    k_logits<<<128, 512>>>(W1, W2);
    k_p<<<2048, 256>>>(dw);
    k_softmax_acc<<<30, 256>>>();
    k_final<<<1, 1>>>(db, out);
}